// round 12
// baseline (speedup 1.0000x reference)
#include <cuda_runtime.h>
#include <cstdint>

#define M_NODES 150000      // 3 * NATOMS
#define NE_EDGES 1500000
#define NE_HALF  750000
#define NHEADS 4
#define DHEAD 16

typedef unsigned long long ull;

// Device-global scratch
__device__ float g_t4[M_NODES * 4];       // per-node low-rank features
__device__ float g_UZ[M_NODES * 20];      // [4 heads x 4 U] + [4 Z]
__device__ float g_A[256];                // A[d*4+i] = (W2@W)[i,d]  (for out_kernel)
__device__ float g_c[64];                 // c[d] = (b2@W + b)[d]    (for out_kernel)
// P tensor, dup-packed: g_P[h*272 + k*16 + p] = dup(P^h_{p,k}); p in 0..14, pad p=15
__device__ ull   g_P[4 * 17 * 16];
__device__ int   g_idx_is_64;

__device__ __forceinline__ float elu1(float v) {
    return v > 0.0f ? v : (__expf(v) - 1.0f);
}

__device__ __forceinline__ void red_add_v4(float* addr, float4 v) {
    asm volatile("red.global.add.v4.f32 [%0], {%1, %2, %3, %4};"
                 :: "l"(addr), "f"(v.x), "f"(v.y), "f"(v.z), "f"(v.w)
                 : "memory");
}

// packed f32x2 helpers (Blackwell): FFMA2 via PTX only
__device__ __forceinline__ ull pk2(float lo, float hi) {
    ull r; asm("mov.b64 %0, {%1, %2};" : "=l"(r) : "f"(lo), "f"(hi)); return r;
}
__device__ __forceinline__ void upk2(float& lo, float& hi, ull v) {
    asm("mov.b64 {%0, %1}, %2;" : "=f"(lo), "=f"(hi) : "l"(v));
}
__device__ __forceinline__ void fma2(ull& d, ull a, ull b) {   // d = a*b + d
    asm("fma.rn.f32x2 %0, %1, %2, %0;" : "+l"(d) : "l"(a), "l"(b));
}
__device__ __forceinline__ ull mul2(ull a, ull b) {
    ull r; asm("mul.rn.f32x2 %0, %1, %2;" : "=l"(r) : "l"(a), "l"(b)); return r;
}
__device__ __forceinline__ ull dupf(float v) {
    uint32_t b = __float_as_uint(v);
    return (ull)b | ((ull)b << 32);
}

// (i,j) pair enumeration, i<=j, p = 0..14
__device__ __constant__ int c_PI[15] = {0,0,0,0,0,1,1,1,1,2,2,2,3,3,4};
__device__ __constant__ int c_PJ[15] = {0,1,2,3,4,1,2,3,4,2,3,4,3,4,4};

// ---------------------------------------------------------------------------
__global__ void probe_idx_kernel(const int* __restrict__ ei32) {
    int z = (ei32[1] == 0) & (ei32[3] == 0) & (ei32[5] == 0) & (ei32[7] == 0);
    g_idx_is_64 = z;
}

// ---------------------------------------------------------------------------
// Setup: A = W2@W, c = b2@W + b, and the trilinear tensor
//   P^h_{p=(i,j),k} = sum_{d in head h} At[i][d]*At[j][d]*Wt[k][d]
// with At = [A rows; c], Wt = [W rows; b].
// ---------------------------------------------------------------------------
__global__ void setup_kernel(const float* __restrict__ W2, const float* __restrict__ b2,
                             const float* __restrict__ W,  const float* __restrict__ b) {
    __shared__ float shA[5 * 64];       // At[i][d], i-major
    int t = threadIdx.x;                // 256 threads; t = d*4 + i
    int d = t >> 2, i = t & 3;
    float a = 0.f;
#pragma unroll
    for (int k = 0; k < 16; k++) a = fmaf(W2[i * 16 + k], W[k * 64 + d], a);
    shA[i * 64 + d] = a;
    if (i == 0) {
        float cc = b[d];
#pragma unroll
        for (int k = 0; k < 16; k++) cc = fmaf(b2[k], W[k * 64 + d], cc);
        shA[4 * 64 + d] = cc;
    }
    __syncthreads();

    // legacy layout for out_kernel
    g_A[t] = shA[i * 64 + d];           // t = d*4+i
    if (t < 64) g_c[t] = shA[4 * 64 + t];

    // P entries: 4 heads x 17 k x 15 p = 1020
    for (int idx = t; idx < 1020; idx += 256) {
        int h   = idx / 255;
        int rem = idx % 255;
        int k   = rem / 15;
        int p   = rem % 15;
        int pi = c_PI[p], pj = c_PJ[p];
        float s = 0.f;
#pragma unroll
        for (int dd = 0; dd < 16; dd++) {
            int dg = h * 16 + dd;
            float wk = (k < 16) ? W[k * 64 + dg] : b[dg];
            s = fmaf(shA[pi * 64 + dg] * shA[pj * 64 + dg], wk, s);
        }
        g_P[h * 272 + k * 16 + p] = dupf(s);
    }
    // zero the p=15 padding
    for (int idx = t; idx < 68; idx += 256)
        g_P[idx * 16 + 15] = 0ull;
}

// ---------------------------------------------------------------------------
// Kernel A: t4[m] = elu(x*W1 + b1); zero the UZ accumulator row.
// ---------------------------------------------------------------------------
__global__ __launch_bounds__(256)
void t4_kernel(const float* __restrict__ ev,
               const float* __restrict__ W1, const float* __restrict__ b1) {
    __shared__ float sW1[4], sb1[4];
    int t = threadIdx.x;
    if (t < 4) { sW1[t] = W1[t]; sb1[t] = b1[t]; }
    __syncthreads();

    int m = blockIdx.x * blockDim.x + t;
    if (m >= M_NODES) return;

    float x = ev[m];
    float4 t4;
    t4.x = elu1(fmaf(x, sW1[0], sb1[0]));
    t4.y = elu1(fmaf(x, sW1[1], sb1[1]));
    t4.z = elu1(fmaf(x, sW1[2], sb1[2]));
    t4.w = elu1(fmaf(x, sW1[3], sb1[3]));
    reinterpret_cast<float4*>(g_t4)[m] = t4;

    float4 z4 = make_float4(0.f, 0.f, 0.f, 0.f);
    float4* uz = reinterpret_cast<float4*>(g_UZ + (size_t)m * 20);
#pragma unroll
    for (int k = 0; k < 5; k++) uz[k] = z4;
}

// ---------------------------------------------------------------------------
// Kernel B: TWO edges per thread, f32x2 lanes = (edgeA, edgeB) end-to-end.
// score_h = sum_p m_p * G_p,  G_p = sum_k e~_k * P^h[k][p]  (P dup-packed).
// ---------------------------------------------------------------------------
__global__ __launch_bounds__(128)
void edge_kernel(const void* __restrict__ ei_raw,
                 const float* __restrict__ ef,
                 const float* __restrict__ W2, const float* __restrict__ b2) {
    __shared__ ull   sP[1088];         // 8.5 KB
    __shared__ float sW2[64], sb2[16];

    int t = threadIdx.x;
    for (int i = t; i < 1088; i += 128) sP[i] = g_P[i];
    if (t < 64) sW2[t] = W2[t];
    if (t < 16) sb2[t] = b2[t];
    __syncthreads();

    int ea = blockIdx.x * blockDim.x + t;
    if (ea >= NE_HALF) return;
    int eb = ea + NE_HALF;

    int srcA, dstA, srcB, dstB;
    if (g_idx_is_64) {
        const long long* ei = (const long long*)ei_raw;
        srcA = (int)__ldg(ei + ea);
        dstA = (int)__ldg(ei + NE_EDGES + ea);
        srcB = (int)__ldg(ei + eb);
        dstB = (int)__ldg(ei + NE_EDGES + eb);
    } else {
        const int* ei = (const int*)ei_raw;
        srcA = __ldg(ei + ea);
        dstA = __ldg(ei + NE_EDGES + ea);
        srcB = __ldg(ei + eb);
        dstB = __ldg(ei + NE_EDGES + eb);
    }

    // front-batch all gathers (MLP)
    float4 tsvA = __ldg(reinterpret_cast<const float4*>(g_t4) + srcA);
    float4 tqvA = __ldg(reinterpret_cast<const float4*>(g_t4) + dstA);
    float4 tsvB = __ldg(reinterpret_cast<const float4*>(g_t4) + srcB);
    float4 tqvB = __ldg(reinterpret_cast<const float4*>(g_t4) + dstB);
    float4 fA = __ldg(reinterpret_cast<const float4*>(ef) + ea);
    float4 fB = __ldg(reinterpret_cast<const float4*>(ef) + eb);

    // e16 for both edges, lanes = (A,B)
    ull e2[16];
#pragma unroll
    for (int k = 0; k < 16; k++) {
        float w0 = sW2[0 * 16 + k], w1 = sW2[1 * 16 + k];
        float w2 = sW2[2 * 16 + k], w3 = sW2[3 * 16 + k];
        float bb = sb2[k];
        float va = bb, vb = bb;
        va = fmaf(fA.x, w0, va); vb = fmaf(fB.x, w0, vb);
        va = fmaf(fA.y, w1, va); vb = fmaf(fB.y, w1, vb);
        va = fmaf(fA.z, w2, va); vb = fmaf(fB.z, w2, vb);
        va = fmaf(fA.w, w3, va); vb = fmaf(fB.w, w3, vb);
        e2[k] = pk2(elu1(va), elu1(vb));
    }

    // extended ts~/tq~ packed (A,B); index 4 is the constant 1
    ull one2 = dupf(1.0f);
    ull ts2[5] = {pk2(tsvA.x, tsvB.x), pk2(tsvA.y, tsvB.y),
                  pk2(tsvA.z, tsvB.z), pk2(tsvA.w, tsvB.w), one2};
    ull tq2[5] = {pk2(tqvA.x, tqvB.x), pk2(tqvA.y, tqvB.y),
                  pk2(tqvA.z, tqvB.z), pk2(tqvA.w, tqvB.w), one2};

    // m_p = ts~_i tq~_j + ts~_j tq~_i (i<j) ; ts~_i tq~_i (i==j)
    ull m2[15];
#pragma unroll
    for (int p = 0; p < 15; p++) {
        int i = c_PI[p], j = c_PJ[p];
        if (i == j) {
            m2[p] = mul2(ts2[i], tq2[i]);
        } else {
            ull v = mul2(ts2[i], tq2[j]);
            fma2(v, ts2[j], tq2[i]);
            m2[p] = v;
        }
    }

    float tsA[4] = {tsvA.x, tsvA.y, tsvA.z, tsvA.w};
    float tsB[4] = {tsvB.x, tsvB.y, tsvB.z, tsvB.w};
    float* uzA = g_UZ + (size_t)dstA * 20;
    float* uzB = g_UZ + (size_t)dstB * 20;
    float zaccA[NHEADS], zaccB[NHEADS];

#pragma unroll
    for (int h = 0; h < NHEADS; h++) {
        const ull* Ph = sP + h * 272;

        // init G from the bias row (k = 16, e~ = 1)
        ull G[15];
        {
            const ulonglong2* r = reinterpret_cast<const ulonglong2*>(Ph + 16 * 16);
#pragma unroll
            for (int q = 0; q < 7; q++) {
                ulonglong2 v = r[q];
                G[2 * q] = v.x; G[2 * q + 1] = v.y;
            }
            G[14] = Ph[16 * 16 + 14];
        }
        // accumulate over k = 0..15
#pragma unroll
        for (int k = 0; k < 16; k++) {
            const ulonglong2* r = reinterpret_cast<const ulonglong2*>(Ph + k * 16);
            ull ek = e2[k];
#pragma unroll
            for (int q = 0; q < 7; q++) {
                ulonglong2 v = r[q];
                fma2(G[2 * q],     ek, v.x);
                fma2(G[2 * q + 1], ek, v.y);
            }
            fma2(G[14], ek, Ph[k * 16 + 14]);
        }
        // score (both lanes at once)
        ull sc2 = mul2(m2[0], G[0]);
#pragma unroll
        for (int p = 1; p < 15; p++) fma2(sc2, m2[p], G[p]);

        float scA, scB;
        upk2(scA, scB, sc2);

        scA *= 0.25f;
        scA = fminf(fmaxf(scA, -5.0f), 5.0f);
        float wA = __expf(scA);
        zaccA[h] = wA;
        red_add_v4(uzA + h * 4,
                   make_float4(tsA[0] * wA, tsA[1] * wA, tsA[2] * wA, tsA[3] * wA));

        scB *= 0.25f;
        scB = fminf(fmaxf(scB, -5.0f), 5.0f);
        float wB = __expf(scB);
        zaccB[h] = wB;
        red_add_v4(uzB + h * 4,
                   make_float4(tsB[0] * wB, tsB[1] * wB, tsB[2] * wB, tsB[3] * wB));
    }
    red_add_v4(uzA + 16, make_float4(zaccA[0], zaccA[1], zaccA[2], zaccA[3]));
    red_add_v4(uzB + 16, make_float4(zaccB[0], zaccB[1], zaccB[2], zaccB[3]));
}

// ---------------------------------------------------------------------------
// Kernel C: wV_d = A[:,d].U_h + c_d*Z_h ; h_d = wV_d/(Z_h+1e-6);
//           out = elu(h @ Wout + bout) @ Wout1 + bout1
// ---------------------------------------------------------------------------
__global__ __launch_bounds__(256)
void out_kernel(float* __restrict__ out,
                const float* __restrict__ Wout,  const float* __restrict__ bout,
                const float* __restrict__ Wout1, const float* __restrict__ bout1) {
    __shared__ float sWo[1024], sbo[16], sW1[16], sb1, sA[256], sc_[64];
    int t = threadIdx.x;
    for (int i = t; i < 1024; i += blockDim.x) sWo[i] = Wout[i];
    if (t < 16) { sbo[t] = bout[t]; sW1[t] = Wout1[t]; }
    if (t == 0) sb1 = bout1[0];
    if (t < 256) sA[t] = g_A[t];
    if (t < 64)  sc_[t] = g_c[t];
    __syncthreads();

    int m = blockIdx.x * blockDim.x + t;
    if (m >= M_NODES) return;

    const float4* uz4 = reinterpret_cast<const float4*>(g_UZ + (size_t)m * 20);
    float4 U0 = uz4[0], U1 = uz4[1], U2 = uz4[2], U3 = uz4[3], Zv = uz4[4];
    float U[NHEADS][4] = {
        {U0.x, U0.y, U0.z, U0.w}, {U1.x, U1.y, U1.z, U1.w},
        {U2.x, U2.y, U2.z, U2.w}, {U3.x, U3.y, U3.z, U3.w}};
    float Z[NHEADS] = {Zv.x, Zv.y, Zv.z, Zv.w};

    float acc[16];
#pragma unroll
    for (int k = 0; k < 16; k++) acc[k] = sbo[k];

#pragma unroll
    for (int h = 0; h < NHEADS; h++) {
        float rz = 1.0f / (Z[h] + 1e-6f);
#pragma unroll
        for (int dd = 0; dd < 16; dd++) {
            int d = h * 16 + dd;
            float wv = sc_[d] * Z[h];
#pragma unroll
            for (int i = 0; i < 4; i++) wv = fmaf(sA[d * 4 + i], U[h][i], wv);
            float hv = wv * rz;
#pragma unroll
            for (int k = 0; k < 16; k++) acc[k] = fmaf(hv, sWo[d * 16 + k], acc[k]);
        }
    }

    float val = sb1;
#pragma unroll
    for (int k = 0; k < 16; k++) {
        float a = elu1(acc[k]);
        val = fmaf(a, sW1[k], val);
    }
    out[m] = val;
}

// ---------------------------------------------------------------------------
extern "C" void kernel_launch(void* const* d_in, const int* in_sizes, int n_in,
                              void* d_out, int out_size) {
    // order: node_attr, edge_index, edge_feature, edge_vector,
    //        W1, b1, W2, b2, W, b, Wout, bout, Wout1, bout1
    const void*  ei   = d_in[1];
    const float* ef   = (const float*)d_in[2];
    const float* ev   = (const float*)d_in[3];
    const float* W1   = (const float*)d_in[4];
    const float* b1   = (const float*)d_in[5];
    const float* W2   = (const float*)d_in[6];
    const float* b2   = (const float*)d_in[7];
    const float* W    = (const float*)d_in[8];
    const float* b    = (const float*)d_in[9];
    const float* Wout = (const float*)d_in[10];
    const float* bout = (const float*)d_in[11];
    const float* Wout1= (const float*)d_in[12];
    const float* bout1= (const float*)d_in[13];
    float* out = (float*)d_out;

    probe_idx_kernel<<<1, 1>>>((const int*)ei);
    setup_kernel<<<1, 256>>>(W2, b2, W, b);
    t4_kernel<<<(M_NODES + 255) / 256, 256>>>(ev, W1, b1);
    edge_kernel<<<(NE_HALF + 127) / 128, 128>>>(ei, ef, W2, b2);
    out_kernel<<<(M_NODES + 255) / 256, 256>>>(out, Wout, bout, Wout1, bout1);
}

// round 13
// speedup vs baseline: 1.0841x; 1.0841x over previous
#include <cuda_runtime.h>
#include <cstdint>

#define M_NODES 150000      // 3 * NATOMS
#define NE_EDGES 1500000
#define NE_QUARTER 375000
#define NHEADS 4
#define DHEAD 16

typedef unsigned long long ull;

// Device-global scratch
__device__ float g_t4[M_NODES * 4];       // per-node low-rank features
__device__ float g_UZ[M_NODES * 20];      // [4 heads x 4 U] + [4 Z]
__device__ float g_A[256];                // A[d*4+i] = (W2@W)[i,d]  (for out_kernel)
__device__ float g_c[64];                 // c[d] = (b2@W + b)[d]    (for out_kernel)
// P tensor, dup-packed, k-major: g_P[k*64 + h*16 + p] = dup(P^h_{p,k}); p 0..14, pad 15
__device__ ull   g_P[17 * 4 * 16];
__device__ int   g_idx_is_64;

__device__ __forceinline__ float elu1(float v) {
    return v > 0.0f ? v : (__expf(v) - 1.0f);
}

__device__ __forceinline__ void red_add_v4(float* addr, float4 v) {
    asm volatile("red.global.add.v4.f32 [%0], {%1, %2, %3, %4};"
                 :: "l"(addr), "f"(v.x), "f"(v.y), "f"(v.z), "f"(v.w)
                 : "memory");
}

// packed f32x2 helpers (Blackwell): FFMA2 via PTX only
__device__ __forceinline__ ull pk2(float lo, float hi) {
    ull r; asm("mov.b64 %0, {%1, %2};" : "=l"(r) : "f"(lo), "f"(hi)); return r;
}
__device__ __forceinline__ void upk2(float& lo, float& hi, ull v) {
    asm("mov.b64 {%0, %1}, %2;" : "=f"(lo), "=f"(hi) : "l"(v));
}
__device__ __forceinline__ void fma2(ull& d, ull a, ull b) {   // d = a*b + d
    asm("fma.rn.f32x2 %0, %1, %2, %0;" : "+l"(d) : "l"(a), "l"(b));
}
__device__ __forceinline__ ull mul2(ull a, ull b) {
    ull r; asm("mul.rn.f32x2 %0, %1, %2;" : "=l"(r) : "l"(a), "l"(b)); return r;
}
__device__ __forceinline__ ull add2(ull a, ull b) {
    ull r; asm("add.rn.f32x2 %0, %1, %2;" : "=l"(r) : "l"(a), "l"(b)); return r;
}
__device__ __forceinline__ ull dupf(float v) {
    uint32_t b = __float_as_uint(v);
    return (ull)b | ((ull)b << 32);
}

// (i,j) pair enumeration, i<=j, p = 0..14
__device__ __constant__ int c_PI[15] = {0,0,0,0,0,1,1,1,1,2,2,2,3,3,4};
__device__ __constant__ int c_PJ[15] = {0,1,2,3,4,1,2,3,4,2,3,4,3,4,4};

// ---------------------------------------------------------------------------
__global__ void probe_idx_kernel(const int* __restrict__ ei32) {
    int z = (ei32[1] == 0) & (ei32[3] == 0) & (ei32[5] == 0) & (ei32[7] == 0);
    g_idx_is_64 = z;
}

// ---------------------------------------------------------------------------
// Setup: A = W2@W, c = b2@W + b, and the trilinear tensor
//   P^h_{p=(i,j),k} = sum_{d in head h} At[i][d]*At[j][d]*Wt[k][d]
// with At = [A rows; c], Wt = [W rows; b]. Stored k-major, dup-packed.
// ---------------------------------------------------------------------------
__global__ void setup_kernel(const float* __restrict__ W2, const float* __restrict__ b2,
                             const float* __restrict__ W,  const float* __restrict__ b) {
    __shared__ float shA[5 * 64];       // At[i][d], i-major
    int t = threadIdx.x;                // 256 threads; t = d*4 + i
    int d = t >> 2, i = t & 3;
    float a = 0.f;
#pragma unroll
    for (int k = 0; k < 16; k++) a = fmaf(W2[i * 16 + k], W[k * 64 + d], a);
    shA[i * 64 + d] = a;
    if (i == 0) {
        float cc = b[d];
#pragma unroll
        for (int k = 0; k < 16; k++) cc = fmaf(b2[k], W[k * 64 + d], cc);
        shA[4 * 64 + d] = cc;
    }
    __syncthreads();

    // legacy layout for out_kernel
    g_A[t] = shA[i * 64 + d];           // t = d*4+i
    if (t < 64) g_c[t] = shA[4 * 64 + t];

    // P entries: 4 heads x 17 k x 15 p = 1020, stored [k][h][p]
    for (int idx = t; idx < 1020; idx += 256) {
        int h   = idx / 255;
        int rem = idx % 255;
        int k   = rem / 15;
        int p   = rem % 15;
        int pi = c_PI[p], pj = c_PJ[p];
        float s = 0.f;
#pragma unroll
        for (int dd = 0; dd < 16; dd++) {
            int dg = h * 16 + dd;
            float wk = (k < 16) ? W[k * 64 + dg] : b[dg];
            s = fmaf(shA[pi * 64 + dg] * shA[pj * 64 + dg], wk, s);
        }
        g_P[k * 64 + h * 16 + p] = dupf(s);
    }
    // zero the p=15 padding: idx = k*4+h -> idx*16+15 = k*64+h*16+15
    for (int idx = t; idx < 68; idx += 256)
        g_P[idx * 16 + 15] = 0ull;
}

// ---------------------------------------------------------------------------
// Kernel A: t4[m] = elu(x*W1 + b1); zero the UZ accumulator row.
// ---------------------------------------------------------------------------
__global__ __launch_bounds__(256)
void t4_kernel(const float* __restrict__ ev,
               const float* __restrict__ W1, const float* __restrict__ b1) {
    __shared__ float sW1[4], sb1[4];
    int t = threadIdx.x;
    if (t < 4) { sW1[t] = W1[t]; sb1[t] = b1[t]; }
    __syncthreads();

    int m = blockIdx.x * blockDim.x + t;
    if (m >= M_NODES) return;

    float x = ev[m];
    float4 t4;
    t4.x = elu1(fmaf(x, sW1[0], sb1[0]));
    t4.y = elu1(fmaf(x, sW1[1], sb1[1]));
    t4.z = elu1(fmaf(x, sW1[2], sb1[2]));
    t4.w = elu1(fmaf(x, sW1[3], sb1[3]));
    reinterpret_cast<float4*>(g_t4)[m] = t4;

    float4 z4 = make_float4(0.f, 0.f, 0.f, 0.f);
    float4* uz = reinterpret_cast<float4*>(g_UZ + (size_t)m * 20);
#pragma unroll
    for (int k = 0; k < 5; k++) uz[k] = z4;
}

// ---------------------------------------------------------------------------
// dot2x15: H1 = m1 . Prow, H2 = m2 . Prow  (one P-row load serves both pairs)
// ---------------------------------------------------------------------------
__device__ __forceinline__ void dot2x15(const ull* m1, const ull* m2v,
                                        const ull* Pr, ull& H1, ull& H2) {
    const ulonglong2* r2 = reinterpret_cast<const ulonglong2*>(Pr);
    ulonglong2 q0 = r2[0], q1 = r2[1], q2 = r2[2], q3 = r2[3];
    ulonglong2 q4 = r2[4], q5 = r2[5], q6 = r2[6], q7 = r2[7];

    ull a = mul2(m1[0], q0.x);
    fma2(a, m1[1], q0.y); fma2(a, m1[2], q1.x); fma2(a, m1[3], q1.y); fma2(a, m1[4], q2.x);
    ull b = mul2(m1[5], q2.y);
    fma2(b, m1[6], q3.x); fma2(b, m1[7], q3.y); fma2(b, m1[8], q4.x); fma2(b, m1[9], q4.y);
    ull c = mul2(m1[10], q5.x);
    fma2(c, m1[11], q5.y); fma2(c, m1[12], q6.x); fma2(c, m1[13], q6.y); fma2(c, m1[14], q7.x);
    H1 = add2(add2(a, b), c);

    ull d = mul2(m2v[0], q0.x);
    fma2(d, m2v[1], q0.y); fma2(d, m2v[2], q1.x); fma2(d, m2v[3], q1.y); fma2(d, m2v[4], q2.x);
    ull e = mul2(m2v[5], q2.y);
    fma2(e, m2v[6], q3.x); fma2(e, m2v[7], q3.y); fma2(e, m2v[8], q4.x); fma2(e, m2v[9], q4.y);
    ull f = mul2(m2v[10], q5.x);
    fma2(f, m2v[11], q5.y); fma2(f, m2v[12], q6.x); fma2(f, m2v[13], q6.y); fma2(f, m2v[14], q7.x);
    H2 = add2(add2(d, e), f);
}

// m_p for an edge pair (lanes = two edges)
__device__ __forceinline__ void make_m(const float4& tsA, const float4& tsB,
                                       const float4& tqA, const float4& tqB, ull* m) {
    ull ts0 = pk2(tsA.x, tsB.x), ts1 = pk2(tsA.y, tsB.y);
    ull ts2 = pk2(tsA.z, tsB.z), ts3 = pk2(tsA.w, tsB.w);
    ull tq0 = pk2(tqA.x, tqB.x), tq1 = pk2(tqA.y, tqB.y);
    ull tq2 = pk2(tqA.z, tqB.z), tq3 = pk2(tqA.w, tqB.w);

    m[0]  = mul2(ts0, tq0);
    m[1]  = mul2(ts0, tq1); fma2(m[1],  ts1, tq0);
    m[2]  = mul2(ts0, tq2); fma2(m[2],  ts2, tq0);
    m[3]  = mul2(ts0, tq3); fma2(m[3],  ts3, tq0);
    m[4]  = add2(ts0, tq0);
    m[5]  = mul2(ts1, tq1);
    m[6]  = mul2(ts1, tq2); fma2(m[6],  ts2, tq1);
    m[7]  = mul2(ts1, tq3); fma2(m[7],  ts3, tq1);
    m[8]  = add2(ts1, tq1);
    m[9]  = mul2(ts2, tq2);
    m[10] = mul2(ts2, tq3); fma2(m[10], ts3, tq2);
    m[11] = add2(ts2, tq2);
    m[12] = mul2(ts3, tq3);
    m[13] = add2(ts3, tq3);
    m[14] = dupf(1.0f);
}

// ---------------------------------------------------------------------------
// Kernel B: FOUR edges per thread (two f32x2 pairs). Every P-row load feeds
// both pairs; e16 computed inside the k-loop (no e2 array state).
// ---------------------------------------------------------------------------
__global__ __launch_bounds__(64)
void edge_kernel(const void* __restrict__ ei_raw,
                 const float* __restrict__ ef,
                 const float* __restrict__ W2, const float* __restrict__ b2) {
    __shared__ ull    sP[1088];        // [k][h][p-dup], 8.5 KB
    __shared__ float4 sW2r[16];        // row k: (W2[0,k],W2[1,k],W2[2,k],W2[3,k])
    __shared__ float  sb2[16];

    int t = threadIdx.x;
    for (int i = t; i < 1088; i += 64) sP[i] = g_P[i];
    if (t < 16) {
        sW2r[t] = make_float4(W2[t], W2[16 + t], W2[32 + t], W2[48 + t]);
        sb2[t] = b2[t];
    }
    __syncthreads();

    int e0 = blockIdx.x * blockDim.x + t;
    if (e0 >= NE_QUARTER) return;
    int e1 = e0 + NE_QUARTER, e2i = e0 + 2 * NE_QUARTER, e3 = e0 + 3 * NE_QUARTER;

    int src0, dst0, src1, dst1, src2, dst2, src3, dst3;
    if (g_idx_is_64) {
        const long long* ei = (const long long*)ei_raw;
        src0 = (int)__ldg(ei + e0);  dst0 = (int)__ldg(ei + NE_EDGES + e0);
        src1 = (int)__ldg(ei + e1);  dst1 = (int)__ldg(ei + NE_EDGES + e1);
        src2 = (int)__ldg(ei + e2i); dst2 = (int)__ldg(ei + NE_EDGES + e2i);
        src3 = (int)__ldg(ei + e3);  dst3 = (int)__ldg(ei + NE_EDGES + e3);
    } else {
        const int* ei = (const int*)ei_raw;
        src0 = __ldg(ei + e0);  dst0 = __ldg(ei + NE_EDGES + e0);
        src1 = __ldg(ei + e1);  dst1 = __ldg(ei + NE_EDGES + e1);
        src2 = __ldg(ei + e2i); dst2 = __ldg(ei + NE_EDGES + e2i);
        src3 = __ldg(ei + e3);  dst3 = __ldg(ei + NE_EDGES + e3);
    }

    const float4* t4p = reinterpret_cast<const float4*>(g_t4);
    float4 ts0 = __ldg(t4p + src0), tq0 = __ldg(t4p + dst0);
    float4 ts1 = __ldg(t4p + src1), tq1 = __ldg(t4p + dst1);
    float4 ts2v = __ldg(t4p + src2), tq2v = __ldg(t4p + dst2);
    float4 ts3 = __ldg(t4p + src3), tq3v = __ldg(t4p + dst3);
    float4 ef0 = __ldg(reinterpret_cast<const float4*>(ef) + e0);
    float4 ef1 = __ldg(reinterpret_cast<const float4*>(ef) + e1);
    float4 ef2 = __ldg(reinterpret_cast<const float4*>(ef) + e2i);
    float4 ef3 = __ldg(reinterpret_cast<const float4*>(ef) + e3);

    // m tensors for pair (e0,e1) and (e2,e3)
    ull m01[15], m23[15];
    make_m(ts0, ts1, tq0, tq1, m01);
    make_m(ts2v, ts3, tq2v, tq3v, m23);

    // init scores from bias row (k = 16, e~ = 1)
    ull sc01[NHEADS], sc23[NHEADS];
#pragma unroll
    for (int h = 0; h < NHEADS; h++)
        dot2x15(m01, m23, sP + 16 * 64 + h * 16, sc01[h], sc23[h]);

    // main k loop
#pragma unroll
    for (int k = 0; k < 16; k++) {
        float4 w = sW2r[k];
        float bb = sb2[k];
        float v0 = fmaf(ef0.x, w.x, fmaf(ef0.y, w.y, fmaf(ef0.z, w.z, fmaf(ef0.w, w.w, bb))));
        float v1 = fmaf(ef1.x, w.x, fmaf(ef1.y, w.y, fmaf(ef1.z, w.z, fmaf(ef1.w, w.w, bb))));
        float v2 = fmaf(ef2.x, w.x, fmaf(ef2.y, w.y, fmaf(ef2.z, w.z, fmaf(ef2.w, w.w, bb))));
        float v3 = fmaf(ef3.x, w.x, fmaf(ef3.y, w.y, fmaf(ef3.z, w.z, fmaf(ef3.w, w.w, bb))));
        ull ek01 = pk2(elu1(v0), elu1(v1));
        ull ek23 = pk2(elu1(v2), elu1(v3));
#pragma unroll
        for (int h = 0; h < NHEADS; h++) {
            ull H01, H23;
            dot2x15(m01, m23, sP + k * 64 + h * 16, H01, H23);
            fma2(sc01[h], ek01, H01);
            fma2(sc23[h], ek23, H23);
        }
    }

    // epilogue: exp + scatter
    float* uz0 = g_UZ + (size_t)dst0 * 20;
    float* uz1 = g_UZ + (size_t)dst1 * 20;
    float* uz2 = g_UZ + (size_t)dst2 * 20;
    float* uz3 = g_UZ + (size_t)dst3 * 20;
    float z0[NHEADS], z1[NHEADS], z2[NHEADS], z3[NHEADS];

#pragma unroll
    for (int h = 0; h < NHEADS; h++) {
        float s0, s1, s2, s3;
        upk2(s0, s1, sc01[h]);
        upk2(s2, s3, sc23[h]);
        s0 = fminf(fmaxf(s0 * 0.25f, -5.0f), 5.0f);
        s1 = fminf(fmaxf(s1 * 0.25f, -5.0f), 5.0f);
        s2 = fminf(fmaxf(s2 * 0.25f, -5.0f), 5.0f);
        s3 = fminf(fmaxf(s3 * 0.25f, -5.0f), 5.0f);
        float w0 = __expf(s0), w1 = __expf(s1), w2 = __expf(s2), w3 = __expf(s3);
        z0[h] = w0; z1[h] = w1; z2[h] = w2; z3[h] = w3;
        red_add_v4(uz0 + h * 4, make_float4(ts0.x * w0, ts0.y * w0, ts0.z * w0, ts0.w * w0));
        red_add_v4(uz1 + h * 4, make_float4(ts1.x * w1, ts1.y * w1, ts1.z * w1, ts1.w * w1));
        red_add_v4(uz2 + h * 4, make_float4(ts2v.x * w2, ts2v.y * w2, ts2v.z * w2, ts2v.w * w2));
        red_add_v4(uz3 + h * 4, make_float4(ts3.x * w3, ts3.y * w3, ts3.z * w3, ts3.w * w3));
    }
    red_add_v4(uz0 + 16, make_float4(z0[0], z0[1], z0[2], z0[3]));
    red_add_v4(uz1 + 16, make_float4(z1[0], z1[1], z1[2], z1[3]));
    red_add_v4(uz2 + 16, make_float4(z2[0], z2[1], z2[2], z2[3]));
    red_add_v4(uz3 + 16, make_float4(z3[0], z3[1], z3[2], z3[3]));
}

// ---------------------------------------------------------------------------
// Kernel C: wV_d = A[:,d].U_h + c_d*Z_h ; h_d = wV_d/(Z_h+1e-6);
//           out = elu(h @ Wout + bout) @ Wout1 + bout1
// ---------------------------------------------------------------------------
__global__ __launch_bounds__(256)
void out_kernel(float* __restrict__ out,
                const float* __restrict__ Wout,  const float* __restrict__ bout,
                const float* __restrict__ Wout1, const float* __restrict__ bout1) {
    __shared__ float sWo[1024], sbo[16], sW1[16], sb1, sA[256], sc_[64];
    int t = threadIdx.x;
    for (int i = t; i < 1024; i += blockDim.x) sWo[i] = Wout[i];
    if (t < 16) { sbo[t] = bout[t]; sW1[t] = Wout1[t]; }
    if (t == 0) sb1 = bout1[0];
    if (t < 256) sA[t] = g_A[t];
    if (t < 64)  sc_[t] = g_c[t];
    __syncthreads();

    int m = blockIdx.x * blockDim.x + t;
    if (m >= M_NODES) return;

    const float4* uz4 = reinterpret_cast<const float4*>(g_UZ + (size_t)m * 20);
    float4 U0 = uz4[0], U1 = uz4[1], U2 = uz4[2], U3 = uz4[3], Zv = uz4[4];
    float U[NHEADS][4] = {
        {U0.x, U0.y, U0.z, U0.w}, {U1.x, U1.y, U1.z, U1.w},
        {U2.x, U2.y, U2.z, U2.w}, {U3.x, U3.y, U3.z, U3.w}};
    float Z[NHEADS] = {Zv.x, Zv.y, Zv.z, Zv.w};

    float acc[16];
#pragma unroll
    for (int k = 0; k < 16; k++) acc[k] = sbo[k];

#pragma unroll
    for (int h = 0; h < NHEADS; h++) {
        float rz = 1.0f / (Z[h] + 1e-6f);
#pragma unroll
        for (int dd = 0; dd < 16; dd++) {
            int d = h * 16 + dd;
            float wv = sc_[d] * Z[h];
#pragma unroll
            for (int i = 0; i < 4; i++) wv = fmaf(sA[d * 4 + i], U[h][i], wv);
            float hv = wv * rz;
#pragma unroll
            for (int k = 0; k < 16; k++) acc[k] = fmaf(hv, sWo[d * 16 + k], acc[k]);
        }
    }

    float val = sb1;
#pragma unroll
    for (int k = 0; k < 16; k++) {
        float a = elu1(acc[k]);
        val = fmaf(a, sW1[k], val);
    }
    out[m] = val;
}

// ---------------------------------------------------------------------------
extern "C" void kernel_launch(void* const* d_in, const int* in_sizes, int n_in,
                              void* d_out, int out_size) {
    // order: node_attr, edge_index, edge_feature, edge_vector,
    //        W1, b1, W2, b2, W, b, Wout, bout, Wout1, bout1
    const void*  ei   = d_in[1];
    const float* ef   = (const float*)d_in[2];
    const float* ev   = (const float*)d_in[3];
    const float* W1   = (const float*)d_in[4];
    const float* b1   = (const float*)d_in[5];
    const float* W2   = (const float*)d_in[6];
    const float* b2   = (const float*)d_in[7];
    const float* W    = (const float*)d_in[8];
    const float* b    = (const float*)d_in[9];
    const float* Wout = (const float*)d_in[10];
    const float* bout = (const float*)d_in[11];
    const float* Wout1= (const float*)d_in[12];
    const float* bout1= (const float*)d_in[13];
    float* out = (float*)d_out;

    probe_idx_kernel<<<1, 1>>>((const int*)ei);
    setup_kernel<<<1, 256>>>(W2, b2, W, b);
    t4_kernel<<<(M_NODES + 255) / 256, 256>>>(ev, W1, b1);
    edge_kernel<<<(NE_QUARTER + 63) / 64, 64>>>(ei, ef, W2, b2);
    out_kernel<<<(M_NODES + 255) / 256, 256>>>(out, Wout, bout, Wout1, bout1);
}

// round 14
// speedup vs baseline: 1.1420x; 1.0534x over previous
#include <cuda_runtime.h>
#include <cstdint>

#define M_NODES 150000      // 3 * NATOMS
#define NE_EDGES 1500000
#define NE_QUARTER 375000
#define NHEADS 4
#define DHEAD 16

typedef unsigned long long ull;

// Device-global scratch
__device__ float g_t4[M_NODES * 4];       // per-node low-rank features
__device__ float g_UZ[M_NODES * 20];      // [4 heads x 4 U] + [4 Z]
__device__ float g_A[256];                // A[d*4+i] = (W2@W)[i,d]  (for out_kernel)
__device__ float g_c[64];                 // c[d] = (b2@W + b)[d]    (for out_kernel)
// P tensor, dup-packed, k-major: g_P[k*64 + h*16 + p] = dup(P^h_{p,k}); p 0..14, pad 15
__device__ ull   g_P[17 * 4 * 16];
__device__ int   g_idx_is_64;

__device__ __forceinline__ float elu1(float v) {
    return v > 0.0f ? v : (__expf(v) - 1.0f);
}

__device__ __forceinline__ void red_add_v4(float* addr, float4 v) {
    asm volatile("red.global.add.v4.f32 [%0], {%1, %2, %3, %4};"
                 :: "l"(addr), "f"(v.x), "f"(v.y), "f"(v.z), "f"(v.w)
                 : "memory");
}

// packed f32x2 helpers (Blackwell): FFMA2 via PTX only
__device__ __forceinline__ ull pk2(float lo, float hi) {
    ull r; asm("mov.b64 %0, {%1, %2};" : "=l"(r) : "f"(lo), "f"(hi)); return r;
}
__device__ __forceinline__ void upk2(float& lo, float& hi, ull v) {
    asm("mov.b64 {%0, %1}, %2;" : "=f"(lo), "=f"(hi) : "l"(v));
}
__device__ __forceinline__ void fma2(ull& d, ull a, ull b) {   // d = a*b + d
    asm("fma.rn.f32x2 %0, %1, %2, %0;" : "+l"(d) : "l"(a), "l"(b));
}
__device__ __forceinline__ ull mul2(ull a, ull b) {
    ull r; asm("mul.rn.f32x2 %0, %1, %2;" : "=l"(r) : "l"(a), "l"(b)); return r;
}
__device__ __forceinline__ ull add2(ull a, ull b) {
    ull r; asm("add.rn.f32x2 %0, %1, %2;" : "=l"(r) : "l"(a), "l"(b)); return r;
}
__device__ __forceinline__ ull dupf(float v) {
    uint32_t b = __float_as_uint(v);
    return (ull)b | ((ull)b << 32);
}

// (i,j) pair enumeration, i<=j, p = 0..14
__device__ __constant__ int c_PI[15] = {0,0,0,0,0,1,1,1,1,2,2,2,3,3,4};
__device__ __constant__ int c_PJ[15] = {0,1,2,3,4,1,2,3,4,2,3,4,3,4,4};

// ---------------------------------------------------------------------------
__global__ void probe_idx_kernel(const int* __restrict__ ei32) {
    int z = (ei32[1] == 0) & (ei32[3] == 0) & (ei32[5] == 0) & (ei32[7] == 0);
    g_idx_is_64 = z;
}

// ---------------------------------------------------------------------------
// Setup: A = W2@W, c = b2@W + b, and the trilinear tensor
//   P^h_{p=(i,j),k} = sum_{d in head h} At[i][d]*At[j][d]*Wt[k][d]
// with At = [A rows; c], Wt = [W rows; b]. Stored k-major, dup-packed.
// ---------------------------------------------------------------------------
__global__ void setup_kernel(const float* __restrict__ W2, const float* __restrict__ b2,
                             const float* __restrict__ W,  const float* __restrict__ b) {
    __shared__ float shA[5 * 64];       // At[i][d], i-major
    int t = threadIdx.x;                // 256 threads; t = d*4 + i
    int d = t >> 2, i = t & 3;
    float a = 0.f;
#pragma unroll
    for (int k = 0; k < 16; k++) a = fmaf(W2[i * 16 + k], W[k * 64 + d], a);
    shA[i * 64 + d] = a;
    if (i == 0) {
        float cc = b[d];
#pragma unroll
        for (int k = 0; k < 16; k++) cc = fmaf(b2[k], W[k * 64 + d], cc);
        shA[4 * 64 + d] = cc;
    }
    __syncthreads();

    // legacy layout for out_kernel
    g_A[t] = shA[i * 64 + d];           // t = d*4+i
    if (t < 64) g_c[t] = shA[4 * 64 + t];

    // P entries: 4 heads x 17 k x 15 p = 1020, stored [k][h][p]
    for (int idx = t; idx < 1020; idx += 256) {
        int h   = idx / 255;
        int rem = idx % 255;
        int k   = rem / 15;
        int p   = rem % 15;
        int pi = c_PI[p], pj = c_PJ[p];
        float s = 0.f;
#pragma unroll
        for (int dd = 0; dd < 16; dd++) {
            int dg = h * 16 + dd;
            float wk = (k < 16) ? W[k * 64 + dg] : b[dg];
            s = fmaf(shA[pi * 64 + dg] * shA[pj * 64 + dg], wk, s);
        }
        g_P[k * 64 + h * 16 + p] = dupf(s);
    }
    // zero the p=15 padding: idx = k*4+h -> idx*16+15 = k*64+h*16+15
    for (int idx = t; idx < 68; idx += 256)
        g_P[idx * 16 + 15] = 0ull;
}

// ---------------------------------------------------------------------------
// Kernel A: t4[m] = elu(x*W1 + b1); zero the UZ accumulator row.
// ---------------------------------------------------------------------------
__global__ __launch_bounds__(256)
void t4_kernel(const float* __restrict__ ev,
               const float* __restrict__ W1, const float* __restrict__ b1) {
    __shared__ float sW1[4], sb1[4];
    int t = threadIdx.x;
    if (t < 4) { sW1[t] = W1[t]; sb1[t] = b1[t]; }
    __syncthreads();

    int m = blockIdx.x * blockDim.x + t;
    if (m >= M_NODES) return;

    float x = ev[m];
    float4 t4;
    t4.x = elu1(fmaf(x, sW1[0], sb1[0]));
    t4.y = elu1(fmaf(x, sW1[1], sb1[1]));
    t4.z = elu1(fmaf(x, sW1[2], sb1[2]));
    t4.w = elu1(fmaf(x, sW1[3], sb1[3]));
    reinterpret_cast<float4*>(g_t4)[m] = t4;

    float4 z4 = make_float4(0.f, 0.f, 0.f, 0.f);
    float4* uz = reinterpret_cast<float4*>(g_UZ + (size_t)m * 20);
#pragma unroll
    for (int k = 0; k < 5; k++) uz[k] = z4;
}

// ---------------------------------------------------------------------------
// dot2x14p: H = m . Prow(0..13) + Prow[14]   (m[14] == 1 is implicit)
// One P-row load serves both edge pairs.
// ---------------------------------------------------------------------------
__device__ __forceinline__ void dot2x14p(const ull* m1, const ull* m2v,
                                         const ull* Pr, ull& H1, ull& H2) {
    const ulonglong2* r2 = reinterpret_cast<const ulonglong2*>(Pr);
    ulonglong2 q0 = r2[0], q1 = r2[1], q2 = r2[2], q3 = r2[3];
    ulonglong2 q4 = r2[4], q5 = r2[5], q6 = r2[6], q7 = r2[7];

    ull a = mul2(m1[0], q0.x);
    fma2(a, m1[1], q0.y); fma2(a, m1[2], q1.x); fma2(a, m1[3], q1.y); fma2(a, m1[4], q2.x);
    ull b = mul2(m1[5], q2.y);
    fma2(b, m1[6], q3.x); fma2(b, m1[7], q3.y); fma2(b, m1[8], q4.x); fma2(b, m1[9], q4.y);
    ull c = mul2(m1[10], q5.x);
    fma2(c, m1[11], q5.y); fma2(c, m1[12], q6.x); fma2(c, m1[13], q6.y);
    H1 = add2(add2(a, b), add2(c, q7.x));

    ull d = mul2(m2v[0], q0.x);
    fma2(d, m2v[1], q0.y); fma2(d, m2v[2], q1.x); fma2(d, m2v[3], q1.y); fma2(d, m2v[4], q2.x);
    ull e = mul2(m2v[5], q2.y);
    fma2(e, m2v[6], q3.x); fma2(e, m2v[7], q3.y); fma2(e, m2v[8], q4.x); fma2(e, m2v[9], q4.y);
    ull f = mul2(m2v[10], q5.x);
    fma2(f, m2v[11], q5.y); fma2(f, m2v[12], q6.x); fma2(f, m2v[13], q6.y);
    H2 = add2(add2(d, e), add2(f, q7.x));
}

// m_p for an edge pair (lanes = two edges); 14 entries, m[14]==1 implicit
__device__ __forceinline__ void make_m(const float4& tsA, const float4& tsB,
                                       const float4& tqA, const float4& tqB, ull* m) {
    ull ts0 = pk2(tsA.x, tsB.x), ts1 = pk2(tsA.y, tsB.y);
    ull ts2 = pk2(tsA.z, tsB.z), ts3 = pk2(tsA.w, tsB.w);
    ull tq0 = pk2(tqA.x, tqB.x), tq1 = pk2(tqA.y, tqB.y);
    ull tq2 = pk2(tqA.z, tqB.z), tq3 = pk2(tqA.w, tqB.w);

    m[0]  = mul2(ts0, tq0);
    m[1]  = mul2(ts0, tq1); fma2(m[1],  ts1, tq0);
    m[2]  = mul2(ts0, tq2); fma2(m[2],  ts2, tq0);
    m[3]  = mul2(ts0, tq3); fma2(m[3],  ts3, tq0);
    m[4]  = add2(ts0, tq0);
    m[5]  = mul2(ts1, tq1);
    m[6]  = mul2(ts1, tq2); fma2(m[6],  ts2, tq1);
    m[7]  = mul2(ts1, tq3); fma2(m[7],  ts3, tq1);
    m[8]  = add2(ts1, tq1);
    m[9]  = mul2(ts2, tq2);
    m[10] = mul2(ts2, tq3); fma2(m[10], ts3, tq2);
    m[11] = add2(ts2, tq2);
    m[12] = mul2(ts3, tq3);
    m[13] = add2(ts3, tq3);
}

// ---------------------------------------------------------------------------
// Kernel B: FOUR edges per thread (two f32x2 pairs). Every P-row load feeds
// both pairs. ts re-gathered in the epilogue (not held across the k-loop).
// ---------------------------------------------------------------------------
__global__ __launch_bounds__(64, 6)
void edge_kernel(const void* __restrict__ ei_raw,
                 const float* __restrict__ ef,
                 const float* __restrict__ W2, const float* __restrict__ b2) {
    __shared__ ull    sP[1088];        // [k][h][p-dup], 8.5 KB
    __shared__ float4 sW2r[16];        // row k: (W2[0,k],W2[1,k],W2[2,k],W2[3,k])
    __shared__ float  sb2[16];

    int t = threadIdx.x;
    for (int i = t; i < 1088; i += 64) sP[i] = g_P[i];
    if (t < 16) {
        sW2r[t] = make_float4(W2[t], W2[16 + t], W2[32 + t], W2[48 + t]);
        sb2[t] = b2[t];
    }
    __syncthreads();

    int e0 = blockIdx.x * blockDim.x + t;
    if (e0 >= NE_QUARTER) return;
    int e1 = e0 + NE_QUARTER, e2i = e0 + 2 * NE_QUARTER, e3 = e0 + 3 * NE_QUARTER;

    int src0, dst0, src1, dst1, src2, dst2, src3, dst3;
    if (g_idx_is_64) {
        const long long* ei = (const long long*)ei_raw;
        src0 = (int)__ldg(ei + e0);  dst0 = (int)__ldg(ei + NE_EDGES + e0);
        src1 = (int)__ldg(ei + e1);  dst1 = (int)__ldg(ei + NE_EDGES + e1);
        src2 = (int)__ldg(ei + e2i); dst2 = (int)__ldg(ei + NE_EDGES + e2i);
        src3 = (int)__ldg(ei + e3);  dst3 = (int)__ldg(ei + NE_EDGES + e3);
    } else {
        const int* ei = (const int*)ei_raw;
        src0 = __ldg(ei + e0);  dst0 = __ldg(ei + NE_EDGES + e0);
        src1 = __ldg(ei + e1);  dst1 = __ldg(ei + NE_EDGES + e1);
        src2 = __ldg(ei + e2i); dst2 = __ldg(ei + NE_EDGES + e2i);
        src3 = __ldg(ei + e3);  dst3 = __ldg(ei + NE_EDGES + e3);
    }

    const float4* t4p = reinterpret_cast<const float4*>(g_t4);
    float4 ef0 = __ldg(reinterpret_cast<const float4*>(ef) + e0);
    float4 ef1 = __ldg(reinterpret_cast<const float4*>(ef) + e1);
    float4 ef2 = __ldg(reinterpret_cast<const float4*>(ef) + e2i);
    float4 ef3 = __ldg(reinterpret_cast<const float4*>(ef) + e3);

    // m tensors for pair (e0,e1) and (e2,e3); ts/tq die after this block
    ull m01[14], m23[14];
    {
        float4 ts0 = __ldg(t4p + src0), tq0 = __ldg(t4p + dst0);
        float4 ts1 = __ldg(t4p + src1), tq1 = __ldg(t4p + dst1);
        make_m(ts0, ts1, tq0, tq1, m01);
        float4 ts2v = __ldg(t4p + src2), tq2v = __ldg(t4p + dst2);
        float4 ts3 = __ldg(t4p + src3), tq3v = __ldg(t4p + dst3);
        make_m(ts2v, ts3, tq2v, tq3v, m23);
    }

    // init scores from bias row (k = 16, e~ = 1)
    ull sc01[NHEADS], sc23[NHEADS];
#pragma unroll
    for (int h = 0; h < NHEADS; h++)
        dot2x14p(m01, m23, sP + 16 * 64 + h * 16, sc01[h], sc23[h]);

    // main k loop
#pragma unroll
    for (int k = 0; k < 16; k++) {
        float4 w = sW2r[k];
        float bb = sb2[k];
        float v0 = fmaf(ef0.x, w.x, fmaf(ef0.y, w.y, fmaf(ef0.z, w.z, fmaf(ef0.w, w.w, bb))));
        float v1 = fmaf(ef1.x, w.x, fmaf(ef1.y, w.y, fmaf(ef1.z, w.z, fmaf(ef1.w, w.w, bb))));
        float v2 = fmaf(ef2.x, w.x, fmaf(ef2.y, w.y, fmaf(ef2.z, w.z, fmaf(ef2.w, w.w, bb))));
        float v3 = fmaf(ef3.x, w.x, fmaf(ef3.y, w.y, fmaf(ef3.z, w.z, fmaf(ef3.w, w.w, bb))));
        ull ek01 = pk2(elu1(v0), elu1(v1));
        ull ek23 = pk2(elu1(v2), elu1(v3));
#pragma unroll
        for (int h = 0; h < NHEADS; h++) {
            ull H01, H23;
            dot2x14p(m01, m23, sP + k * 64 + h * 16, H01, H23);
            fma2(sc01[h], ek01, H01);
            fma2(sc23[h], ek23, H23);
        }
    }

    // epilogue: re-gather ts (L1-hot), exp + scatter
    float4 ts0 = __ldg(t4p + src0);
    float4 ts1 = __ldg(t4p + src1);
    float4 ts2v = __ldg(t4p + src2);
    float4 ts3 = __ldg(t4p + src3);

    float* uz0 = g_UZ + (size_t)dst0 * 20;
    float* uz1 = g_UZ + (size_t)dst1 * 20;
    float* uz2 = g_UZ + (size_t)dst2 * 20;
    float* uz3 = g_UZ + (size_t)dst3 * 20;
    float z0[NHEADS], z1[NHEADS], z2[NHEADS], z3[NHEADS];

#pragma unroll
    for (int h = 0; h < NHEADS; h++) {
        float s0, s1, s2, s3;
        upk2(s0, s1, sc01[h]);
        upk2(s2, s3, sc23[h]);
        s0 = fminf(fmaxf(s0 * 0.25f, -5.0f), 5.0f);
        s1 = fminf(fmaxf(s1 * 0.25f, -5.0f), 5.0f);
        s2 = fminf(fmaxf(s2 * 0.25f, -5.0f), 5.0f);
        s3 = fminf(fmaxf(s3 * 0.25f, -5.0f), 5.0f);
        float w0 = __expf(s0), w1 = __expf(s1), w2 = __expf(s2), w3 = __expf(s3);
        z0[h] = w0; z1[h] = w1; z2[h] = w2; z3[h] = w3;
        red_add_v4(uz0 + h * 4, make_float4(ts0.x * w0, ts0.y * w0, ts0.z * w0, ts0.w * w0));
        red_add_v4(uz1 + h * 4, make_float4(ts1.x * w1, ts1.y * w1, ts1.z * w1, ts1.w * w1));
        red_add_v4(uz2 + h * 4, make_float4(ts2v.x * w2, ts2v.y * w2, ts2v.z * w2, ts2v.w * w2));
        red_add_v4(uz3 + h * 4, make_float4(ts3.x * w3, ts3.y * w3, ts3.z * w3, ts3.w * w3));
    }
    red_add_v4(uz0 + 16, make_float4(z0[0], z0[1], z0[2], z0[3]));
    red_add_v4(uz1 + 16, make_float4(z1[0], z1[1], z1[2], z1[3]));
    red_add_v4(uz2 + 16, make_float4(z2[0], z2[1], z2[2], z2[3]));
    red_add_v4(uz3 + 16, make_float4(z3[0], z3[1], z3[2], z3[3]));
}

// ---------------------------------------------------------------------------
// Kernel C: wV_d = A[:,d].U_h + c_d*Z_h ; h_d = wV_d/(Z_h+1e-6);
//           out = elu(h @ Wout + bout) @ Wout1 + bout1
// ---------------------------------------------------------------------------
__global__ __launch_bounds__(256)
void out_kernel(float* __restrict__ out,
                const float* __restrict__ Wout,  const float* __restrict__ bout,
                const float* __restrict__ Wout1, const float* __restrict__ bout1) {
    __shared__ float sWo[1024], sbo[16], sW1[16], sb1, sA[256], sc_[64];
    int t = threadIdx.x;
    for (int i = t; i < 1024; i += blockDim.x) sWo[i] = Wout[i];
    if (t < 16) { sbo[t] = bout[t]; sW1[t] = Wout1[t]; }
    if (t == 0) sb1 = bout1[0];
    if (t < 256) sA[t] = g_A[t];
    if (t < 64)  sc_[t] = g_c[t];
    __syncthreads();

    int m = blockIdx.x * blockDim.x + t;
    if (m >= M_NODES) return;

    const float4* uz4 = reinterpret_cast<const float4*>(g_UZ + (size_t)m * 20);
    float4 U0 = uz4[0], U1 = uz4[1], U2 = uz4[2], U3 = uz4[3], Zv = uz4[4];
    float U[NHEADS][4] = {
        {U0.x, U0.y, U0.z, U0.w}, {U1.x, U1.y, U1.z, U1.w},
        {U2.x, U2.y, U2.z, U2.w}, {U3.x, U3.y, U3.z, U3.w}};
    float Z[NHEADS] = {Zv.x, Zv.y, Zv.z, Zv.w};

    float acc[16];
#pragma unroll
    for (int k = 0; k < 16; k++) acc[k] = sbo[k];

#pragma unroll
    for (int h = 0; h < NHEADS; h++) {
        float rz = 1.0f / (Z[h] + 1e-6f);
#pragma unroll
        for (int dd = 0; dd < 16; dd++) {
            int d = h * 16 + dd;
            float wv = sc_[d] * Z[h];
#pragma unroll
            for (int i = 0; i < 4; i++) wv = fmaf(sA[d * 4 + i], U[h][i], wv);
            float hv = wv * rz;
#pragma unroll
            for (int k = 0; k < 16; k++) acc[k] = fmaf(hv, sWo[d * 16 + k], acc[k]);
        }
    }

    float val = sb1;
#pragma unroll
    for (int k = 0; k < 16; k++) {
        float a = elu1(acc[k]);
        val = fmaf(a, sW1[k], val);
    }
    out[m] = val;
}

// ---------------------------------------------------------------------------
extern "C" void kernel_launch(void* const* d_in, const int* in_sizes, int n_in,
                              void* d_out, int out_size) {
    // order: node_attr, edge_index, edge_feature, edge_vector,
    //        W1, b1, W2, b2, W, b, Wout, bout, Wout1, bout1
    const void*  ei   = d_in[1];
    const float* ef   = (const float*)d_in[2];
    const float* ev   = (const float*)d_in[3];
    const float* W1   = (const float*)d_in[4];
    const float* b1   = (const float*)d_in[5];
    const float* W2   = (const float*)d_in[6];
    const float* b2   = (const float*)d_in[7];
    const float* W    = (const float*)d_in[8];
    const float* b    = (const float*)d_in[9];
    const float* Wout = (const float*)d_in[10];
    const float* bout = (const float*)d_in[11];
    const float* Wout1= (const float*)d_in[12];
    const float* bout1= (const float*)d_in[13];
    float* out = (float*)d_out;

    probe_idx_kernel<<<1, 1>>>((const int*)ei);
    setup_kernel<<<1, 256>>>(W2, b2, W, b);
    t4_kernel<<<(M_NODES + 255) / 256, 256>>>(ev, W1, b1);
    edge_kernel<<<(NE_QUARTER + 63) / 64, 64>>>(ei, ef, W2, b2);
    out_kernel<<<(M_NODES + 255) / 256, 256>>>(out, Wout, bout, Wout1, bout1);
}

// round 15
// speedup vs baseline: 1.1554x; 1.0117x over previous
#include <cuda_runtime.h>
#include <cstdint>

#define M_NODES 150000      // 3 * NATOMS
#define NE_EDGES 1500000
#define NE_HALF  750000
#define NHEADS 4
#define DHEAD 16

typedef unsigned long long ull;

// Device-global scratch
__device__ float g_t4[M_NODES * 4];       // per-node low-rank features
__device__ float g_UZ[M_NODES * 20];      // [4 heads x 4 U] + [4 Z]
__device__ float g_A[256];                // A[d*4+i] = (W2@W)[i,d]  (for out_kernel)
__device__ float g_c[64];                 // c[d] = (b2@W + b)[d]    (for out_kernel)
// P tensor, dup-packed, k-major: g_P[k*64 + h*16 + p] = dup(P^h_{p,k}); p 0..14, pad 15
__device__ ull   g_P[17 * 4 * 16];
__device__ int   g_idx_is_64;

__device__ __forceinline__ float elu1(float v) {
    return v > 0.0f ? v : (__expf(v) - 1.0f);
}

__device__ __forceinline__ void red_add_v4(float* addr, float4 v) {
    asm volatile("red.global.add.v4.f32 [%0], {%1, %2, %3, %4};"
                 :: "l"(addr), "f"(v.x), "f"(v.y), "f"(v.z), "f"(v.w)
                 : "memory");
}

// packed f32x2 helpers (Blackwell): FFMA2 via PTX only
__device__ __forceinline__ ull pk2(float lo, float hi) {
    ull r; asm("mov.b64 %0, {%1, %2};" : "=l"(r) : "f"(lo), "f"(hi)); return r;
}
__device__ __forceinline__ void upk2(float& lo, float& hi, ull v) {
    asm("mov.b64 {%0, %1}, %2;" : "=f"(lo), "=f"(hi) : "l"(v));
}
__device__ __forceinline__ void fma2(ull& d, ull a, ull b) {   // d = a*b + d
    asm("fma.rn.f32x2 %0, %1, %2, %0;" : "+l"(d) : "l"(a), "l"(b));
}
__device__ __forceinline__ ull mul2(ull a, ull b) {
    ull r; asm("mul.rn.f32x2 %0, %1, %2;" : "=l"(r) : "l"(a), "l"(b)); return r;
}
__device__ __forceinline__ ull add2(ull a, ull b) {
    ull r; asm("add.rn.f32x2 %0, %1, %2;" : "=l"(r) : "l"(a), "l"(b)); return r;
}
__device__ __forceinline__ ull dupf(float v) {
    uint32_t b = __float_as_uint(v);
    return (ull)b | ((ull)b << 32);
}

// (i,j) pair enumeration, i<=j, p = 0..14
__device__ __constant__ int c_PI[15] = {0,0,0,0,0,1,1,1,1,2,2,2,3,3,4};
__device__ __constant__ int c_PJ[15] = {0,1,2,3,4,1,2,3,4,2,3,4,3,4,4};

// ---------------------------------------------------------------------------
__global__ void probe_idx_kernel(const int* __restrict__ ei32) {
    int z = (ei32[1] == 0) & (ei32[3] == 0) & (ei32[5] == 0) & (ei32[7] == 0);
    g_idx_is_64 = z;
}

// ---------------------------------------------------------------------------
// Setup: A = W2@W, c = b2@W + b, and the trilinear tensor
//   P^h_{p=(i,j),k} = sum_{d in head h} At[i][d]*At[j][d]*Wt[k][d]
// with At = [A rows; c], Wt = [W rows; b]. Stored k-major, dup-packed.
// ---------------------------------------------------------------------------
__global__ void setup_kernel(const float* __restrict__ W2, const float* __restrict__ b2,
                             const float* __restrict__ W,  const float* __restrict__ b) {
    __shared__ float shA[5 * 64];       // At[i][d], i-major
    int t = threadIdx.x;                // 256 threads; t = d*4 + i
    int d = t >> 2, i = t & 3;
    float a = 0.f;
#pragma unroll
    for (int k = 0; k < 16; k++) a = fmaf(W2[i * 16 + k], W[k * 64 + d], a);
    shA[i * 64 + d] = a;
    if (i == 0) {
        float cc = b[d];
#pragma unroll
        for (int k = 0; k < 16; k++) cc = fmaf(b2[k], W[k * 64 + d], cc);
        shA[4 * 64 + d] = cc;
    }
    __syncthreads();

    // legacy layout for out_kernel
    g_A[t] = shA[i * 64 + d];           // t = d*4+i
    if (t < 64) g_c[t] = shA[4 * 64 + t];

    // P entries: 4 heads x 17 k x 15 p = 1020, stored [k][h][p]
    for (int idx = t; idx < 1020; idx += 256) {
        int h   = idx / 255;
        int rem = idx % 255;
        int k   = rem / 15;
        int p   = rem % 15;
        int pi = c_PI[p], pj = c_PJ[p];
        float s = 0.f;
#pragma unroll
        for (int dd = 0; dd < 16; dd++) {
            int dg = h * 16 + dd;
            float wk = (k < 16) ? W[k * 64 + dg] : b[dg];
            s = fmaf(shA[pi * 64 + dg] * shA[pj * 64 + dg], wk, s);
        }
        g_P[k * 64 + h * 16 + p] = dupf(s);
    }
    // zero the p=15 padding: idx = k*4+h -> idx*16+15 = k*64+h*16+15
    for (int idx = t; idx < 68; idx += 256)
        g_P[idx * 16 + 15] = 0ull;
}

// ---------------------------------------------------------------------------
// Kernel A: t4[m] = elu(x*W1 + b1); zero the UZ accumulator row.
// ---------------------------------------------------------------------------
__global__ __launch_bounds__(256)
void t4_kernel(const float* __restrict__ ev,
               const float* __restrict__ W1, const float* __restrict__ b1) {
    __shared__ float sW1[4], sb1[4];
    int t = threadIdx.x;
    if (t < 4) { sW1[t] = W1[t]; sb1[t] = b1[t]; }
    __syncthreads();

    int m = blockIdx.x * blockDim.x + t;
    if (m >= M_NODES) return;

    float x = ev[m];
    float4 t4;
    t4.x = elu1(fmaf(x, sW1[0], sb1[0]));
    t4.y = elu1(fmaf(x, sW1[1], sb1[1]));
    t4.z = elu1(fmaf(x, sW1[2], sb1[2]));
    t4.w = elu1(fmaf(x, sW1[3], sb1[3]));
    reinterpret_cast<float4*>(g_t4)[m] = t4;

    float4 z4 = make_float4(0.f, 0.f, 0.f, 0.f);
    float4* uz = reinterpret_cast<float4*>(g_UZ + (size_t)m * 20);
#pragma unroll
    for (int k = 0; k < 5; k++) uz[k] = z4;
}

// ---------------------------------------------------------------------------
// dot1x14p: H = m . Prow(0..13) + Prow[14]   (m[14] == 1 implicit)
// Three independent partial chains for issue eligibility.
// ---------------------------------------------------------------------------
__device__ __forceinline__ ull dot1x14p(const ull* m, const ull* Pr) {
    const ulonglong2* r2 = reinterpret_cast<const ulonglong2*>(Pr);
    ulonglong2 q0 = r2[0], q1 = r2[1], q2 = r2[2], q3 = r2[3];
    ulonglong2 q4 = r2[4], q5 = r2[5], q6 = r2[6], q7 = r2[7];

    ull a = mul2(m[0], q0.x);
    fma2(a, m[1], q0.y); fma2(a, m[2], q1.x); fma2(a, m[3], q1.y); fma2(a, m[4], q2.x);
    ull b = mul2(m[5], q2.y);
    fma2(b, m[6], q3.x); fma2(b, m[7], q3.y); fma2(b, m[8], q4.x); fma2(b, m[9], q4.y);
    ull c = mul2(m[10], q5.x);
    fma2(c, m[11], q5.y); fma2(c, m[12], q6.x); fma2(c, m[13], q6.y);
    return add2(add2(a, b), add2(c, q7.x));
}

// m_p for an edge pair (lanes = two edges); 14 entries, m[14]==1 implicit
__device__ __forceinline__ void make_m(const float4& tsA, const float4& tsB,
                                       const float4& tqA, const float4& tqB, ull* m) {
    ull ts0 = pk2(tsA.x, tsB.x), ts1 = pk2(tsA.y, tsB.y);
    ull ts2 = pk2(tsA.z, tsB.z), ts3 = pk2(tsA.w, tsB.w);
    ull tq0 = pk2(tqA.x, tqB.x), tq1 = pk2(tqA.y, tqB.y);
    ull tq2 = pk2(tqA.z, tqB.z), tq3 = pk2(tqA.w, tqB.w);

    m[0]  = mul2(ts0, tq0);
    m[1]  = mul2(ts0, tq1); fma2(m[1],  ts1, tq0);
    m[2]  = mul2(ts0, tq2); fma2(m[2],  ts2, tq0);
    m[3]  = mul2(ts0, tq3); fma2(m[3],  ts3, tq0);
    m[4]  = add2(ts0, tq0);
    m[5]  = mul2(ts1, tq1);
    m[6]  = mul2(ts1, tq2); fma2(m[6],  ts2, tq1);
    m[7]  = mul2(ts1, tq3); fma2(m[7],  ts3, tq1);
    m[8]  = add2(ts1, tq1);
    m[9]  = mul2(ts2, tq2);
    m[10] = mul2(ts2, tq3); fma2(m[10], ts3, tq2);
    m[11] = add2(ts2, tq2);
    m[12] = mul2(ts3, tq3);
    m[13] = add2(ts3, tq3);
}

// ---------------------------------------------------------------------------
// Kernel B: TWO edges per thread (one f32x2 pair), lean state (~85 regs) for
// 20 warps/SM. e16 interleaved into the k-loop; ts re-gathered in epilogue.
// ---------------------------------------------------------------------------
__global__ __launch_bounds__(128, 5)
void edge_kernel(const void* __restrict__ ei_raw,
                 const float* __restrict__ ef,
                 const float* __restrict__ W2, const float* __restrict__ b2) {
    __shared__ ull    sP[1088];        // [k][h][p-dup], 8.5 KB
    __shared__ float4 sW2r[16];        // row k: (W2[0,k],W2[1,k],W2[2,k],W2[3,k])
    __shared__ float  sb2[16];

    int t = threadIdx.x;
    for (int i = t; i < 1088; i += 128) sP[i] = g_P[i];
    if (t < 16) {
        sW2r[t] = make_float4(W2[t], W2[16 + t], W2[32 + t], W2[48 + t]);
        sb2[t] = b2[t];
    }
    __syncthreads();

    int ea = blockIdx.x * blockDim.x + t;
    if (ea >= NE_HALF) return;
    int eb = ea + NE_HALF;

    int srcA, dstA, srcB, dstB;
    if (g_idx_is_64) {
        const long long* ei = (const long long*)ei_raw;
        srcA = (int)__ldg(ei + ea);
        dstA = (int)__ldg(ei + NE_EDGES + ea);
        srcB = (int)__ldg(ei + eb);
        dstB = (int)__ldg(ei + NE_EDGES + eb);
    } else {
        const int* ei = (const int*)ei_raw;
        srcA = __ldg(ei + ea);
        dstA = __ldg(ei + NE_EDGES + ea);
        srcB = __ldg(ei + eb);
        dstB = __ldg(ei + NE_EDGES + eb);
    }

    const float4* t4p = reinterpret_cast<const float4*>(g_t4);
    float4 efA = __ldg(reinterpret_cast<const float4*>(ef) + ea);
    float4 efB = __ldg(reinterpret_cast<const float4*>(ef) + eb);

    // m tensor; ts/tq registers die after this block
    ull m[14];
    {
        float4 tsA = __ldg(t4p + srcA), tqA = __ldg(t4p + dstA);
        float4 tsB = __ldg(t4p + srcB), tqB = __ldg(t4p + dstB);
        make_m(tsA, tsB, tqA, tqB, m);
    }

    // init scores from bias row (k = 16, e~ = 1)
    ull sc[NHEADS];
#pragma unroll
    for (int h = 0; h < NHEADS; h++)
        sc[h] = dot1x14p(m, sP + 16 * 64 + h * 16);

    // main k loop: e16 computed in-loop, accumulated straight into sc
#pragma unroll
    for (int k = 0; k < 16; k++) {
        float4 w = sW2r[k];
        float bb = sb2[k];
        float va = fmaf(efA.x, w.x, fmaf(efA.y, w.y, fmaf(efA.z, w.z, fmaf(efA.w, w.w, bb))));
        float vb = fmaf(efB.x, w.x, fmaf(efB.y, w.y, fmaf(efB.z, w.z, fmaf(efB.w, w.w, bb))));
        ull ek = pk2(elu1(va), elu1(vb));
#pragma unroll
        for (int h = 0; h < NHEADS; h++) {
            ull H = dot1x14p(m, sP + k * 64 + h * 16);
            fma2(sc[h], ek, H);
        }
    }

    // epilogue: re-gather ts (L1-hot), exp + scatter
    float4 tsA = __ldg(t4p + srcA);
    float4 tsB = __ldg(t4p + srcB);

    float* uzA = g_UZ + (size_t)dstA * 20;
    float* uzB = g_UZ + (size_t)dstB * 20;
    float zA[NHEADS], zB[NHEADS];

#pragma unroll
    for (int h = 0; h < NHEADS; h++) {
        float sA, sB;
        upk2(sA, sB, sc[h]);
        sA = fminf(fmaxf(sA * 0.25f, -5.0f), 5.0f);
        sB = fminf(fmaxf(sB * 0.25f, -5.0f), 5.0f);
        float wA = __expf(sA), wB = __expf(sB);
        zA[h] = wA; zB[h] = wB;
        red_add_v4(uzA + h * 4, make_float4(tsA.x * wA, tsA.y * wA, tsA.z * wA, tsA.w * wA));
        red_add_v4(uzB + h * 4, make_float4(tsB.x * wB, tsB.y * wB, tsB.z * wB, tsB.w * wB));
    }
    red_add_v4(uzA + 16, make_float4(zA[0], zA[1], zA[2], zA[3]));
    red_add_v4(uzB + 16, make_float4(zB[0], zB[1], zB[2], zB[3]));
}

// ---------------------------------------------------------------------------
// Kernel C: wV_d = A[:,d].U_h + c_d*Z_h ; h_d = wV_d/(Z_h+1e-6);
//           out = elu(h @ Wout + bout) @ Wout1 + bout1
// ---------------------------------------------------------------------------
__global__ __launch_bounds__(256)
void out_kernel(float* __restrict__ out,
                const float* __restrict__ Wout,  const float* __restrict__ bout,
                const float* __restrict__ Wout1, const float* __restrict__ bout1) {
    __shared__ float sWo[1024], sbo[16], sW1[16], sb1, sA[256], sc_[64];
    int t = threadIdx.x;
    for (int i = t; i < 1024; i += blockDim.x) sWo[i] = Wout[i];
    if (t < 16) { sbo[t] = bout[t]; sW1[t] = Wout1[t]; }
    if (t == 0) sb1 = bout1[0];
    if (t < 256) sA[t] = g_A[t];
    if (t < 64)  sc_[t] = g_c[t];
    __syncthreads();

    int m = blockIdx.x * blockDim.x + t;
    if (m >= M_NODES) return;

    const float4* uz4 = reinterpret_cast<const float4*>(g_UZ + (size_t)m * 20);
    float4 U0 = uz4[0], U1 = uz4[1], U2 = uz4[2], U3 = uz4[3], Zv = uz4[4];
    float U[NHEADS][4] = {
        {U0.x, U0.y, U0.z, U0.w}, {U1.x, U1.y, U1.z, U1.w},
        {U2.x, U2.y, U2.z, U2.w}, {U3.x, U3.y, U3.z, U3.w}};
    float Z[NHEADS] = {Zv.x, Zv.y, Zv.z, Zv.w};

    float acc[16];
#pragma unroll
    for (int k = 0; k < 16; k++) acc[k] = sbo[k];

#pragma unroll
    for (int h = 0; h < NHEADS; h++) {
        float rz = 1.0f / (Z[h] + 1e-6f);
#pragma unroll
        for (int dd = 0; dd < 16; dd++) {
            int d = h * 16 + dd;
            float wv = sc_[d] * Z[h];
#pragma unroll
            for (int i = 0; i < 4; i++) wv = fmaf(sA[d * 4 + i], U[h][i], wv);
            float hv = wv * rz;
#pragma unroll
            for (int k = 0; k < 16; k++) acc[k] = fmaf(hv, sWo[d * 16 + k], acc[k]);
        }
    }

    float val = sb1;
#pragma unroll
    for (int k = 0; k < 16; k++) {
        float a = elu1(acc[k]);
        val = fmaf(a, sW1[k], val);
    }
    out[m] = val;
}

// ---------------------------------------------------------------------------
extern "C" void kernel_launch(void* const* d_in, const int* in_sizes, int n_in,
                              void* d_out, int out_size) {
    // order: node_attr, edge_index, edge_feature, edge_vector,
    //        W1, b1, W2, b2, W, b, Wout, bout, Wout1, bout1
    const void*  ei   = d_in[1];
    const float* ef   = (const float*)d_in[2];
    const float* ev   = (const float*)d_in[3];
    const float* W1   = (const float*)d_in[4];
    const float* b1   = (const float*)d_in[5];
    const float* W2   = (const float*)d_in[6];
    const float* b2   = (const float*)d_in[7];
    const float* W    = (const float*)d_in[8];
    const float* b    = (const float*)d_in[9];
    const float* Wout = (const float*)d_in[10];
    const float* bout = (const float*)d_in[11];
    const float* Wout1= (const float*)d_in[12];
    const float* bout1= (const float*)d_in[13];
    float* out = (float*)d_out;

    probe_idx_kernel<<<1, 1>>>((const int*)ei);
    setup_kernel<<<1, 256>>>(W2, b2, W, b);
    t4_kernel<<<(M_NODES + 255) / 256, 256>>>(ev, W1, b1);
    edge_kernel<<<(NE_HALF + 127) / 128, 128>>>(ei, ef, W2, b2);
    out_kernel<<<(M_NODES + 255) / 256, 256>>>(out, Wout, bout, Wout1, bout1);
}

// round 16
// speedup vs baseline: 1.4780x; 1.2793x over previous
#include <cuda_runtime.h>
#include <cstdint>

#define M_NODES 150000      // 3 * NATOMS
#define NE_EDGES 1500000
#define NE_HALF  750000
#define NHEADS 4
#define DHEAD 16

typedef unsigned long long ull;

// Device-global scratch
__device__ float g_t4[M_NODES * 4];       // per-node low-rank features
__device__ float g_UZ[M_NODES * 20];      // [4 heads x 4 U] + [4 Z]
__device__ float g_A[256];                // A[d*4+i] = (W2@W)[i,d]  (for out_kernel)
__device__ float g_c[64];                 // c[d] = (b2@W + b)[d]    (for out_kernel)
// P tensor packed by HEAD PAIR: g_P2[k*32 + hp*16 + p] = (P^{2hp}_{p,k}, P^{2hp+1}_{p,k})
// k in 0..16 (16 = bias row), hp in 0..1, p in 0..14 (+pad 15)
__device__ ull   g_P2[17 * 2 * 16];
__device__ int   g_idx_is_64;

__device__ __forceinline__ float elu1(float v) {
    return v > 0.0f ? v : (__expf(v) - 1.0f);
}

__device__ __forceinline__ void red_add_v4(float* addr, float4 v) {
    asm volatile("red.global.add.v4.f32 [%0], {%1, %2, %3, %4};"
                 :: "l"(addr), "f"(v.x), "f"(v.y), "f"(v.z), "f"(v.w)
                 : "memory");
}

// packed f32x2 helpers (Blackwell): FFMA2 via PTX only
__device__ __forceinline__ ull pk2(float lo, float hi) {
    ull r; asm("mov.b64 %0, {%1, %2};" : "=l"(r) : "f"(lo), "f"(hi)); return r;
}
__device__ __forceinline__ void upk2(float& lo, float& hi, ull v) {
    asm("mov.b64 {%0, %1}, %2;" : "=f"(lo), "=f"(hi) : "l"(v));
}
__device__ __forceinline__ void fma2(ull& d, ull a, ull b) {   // d = a*b + d
    asm("fma.rn.f32x2 %0, %1, %2, %0;" : "+l"(d) : "l"(a), "l"(b));
}
__device__ __forceinline__ ull mul2(ull a, ull b) {
    ull r; asm("mul.rn.f32x2 %0, %1, %2;" : "=l"(r) : "l"(a), "l"(b)); return r;
}
__device__ __forceinline__ ull add2(ull a, ull b) {
    ull r; asm("add.rn.f32x2 %0, %1, %2;" : "=l"(r) : "l"(a), "l"(b)); return r;
}
__device__ __forceinline__ ull dupf(float v) {
    uint32_t b = __float_as_uint(v);
    return (ull)b | ((ull)b << 32);
}

// (i,j) pair enumeration, i<=j, p = 0..14
__device__ __constant__ int c_PI[15] = {0,0,0,0,0,1,1,1,1,2,2,2,3,3,4};
__device__ __constant__ int c_PJ[15] = {0,1,2,3,4,1,2,3,4,2,3,4,3,4,4};

// ---------------------------------------------------------------------------
__global__ void probe_idx_kernel(const int* __restrict__ ei32) {
    int z = (ei32[1] == 0) & (ei32[3] == 0) & (ei32[5] == 0) & (ei32[7] == 0);
    g_idx_is_64 = z;
}

// ---------------------------------------------------------------------------
// Setup: A = W2@W, c = b2@W + b, and P^h_{p,k} packed by head pair.
// ---------------------------------------------------------------------------
__global__ void setup_kernel(const float* __restrict__ W2, const float* __restrict__ b2,
                             const float* __restrict__ W,  const float* __restrict__ b) {
    __shared__ float shA[5 * 64];       // At[i][d], i-major
    __shared__ float shP[1020];         // shP[(k*4+h)*15 + p]
    int t = threadIdx.x;                // 256 threads; t = d*4 + i
    int d = t >> 2, i = t & 3;
    float a = 0.f;
#pragma unroll
    for (int k = 0; k < 16; k++) a = fmaf(W2[i * 16 + k], W[k * 64 + d], a);
    shA[i * 64 + d] = a;
    if (i == 0) {
        float cc = b[d];
#pragma unroll
        for (int k = 0; k < 16; k++) cc = fmaf(b2[k], W[k * 64 + d], cc);
        shA[4 * 64 + d] = cc;
    }
    __syncthreads();

    // legacy layout for out_kernel
    g_A[t] = shA[i * 64 + d];           // t = d*4+i
    if (t < 64) g_c[t] = shA[4 * 64 + t];

    // P entries: stored scalar in shP
    for (int idx = t; idx < 1020; idx += 256) {
        int h   = idx / 255;
        int rem = idx % 255;
        int k   = rem / 15;
        int p   = rem % 15;
        int pi = c_PI[p], pj = c_PJ[p];
        float s = 0.f;
#pragma unroll
        for (int dd = 0; dd < 16; dd++) {
            int dg = h * 16 + dd;
            float wk = (k < 16) ? W[k * 64 + dg] : b[dg];
            s = fmaf(shA[pi * 64 + dg] * shA[pj * 64 + dg], wk, s);
        }
        shP[(k * 4 + h) * 15 + p] = s;
    }
    __syncthreads();

    // pack head pairs: g_P2[k*32 + hp*16 + p] = (P^{2hp}, P^{2hp+1})
    for (int idx = t; idx < 544; idx += 256) {
        int k  = idx / 32;
        int r  = idx % 32;
        int hp = r / 16;
        int p  = r % 16;
        ull v = 0ull;
        if (p < 15)
            v = pk2(shP[(k * 4 + 2 * hp) * 15 + p], shP[(k * 4 + 2 * hp + 1) * 15 + p]);
        g_P2[idx] = v;
    }
}

// ---------------------------------------------------------------------------
// Kernel A: t4[m] = elu(x*W1 + b1); zero the UZ accumulator row.
// ---------------------------------------------------------------------------
__global__ __launch_bounds__(256)
void t4_kernel(const float* __restrict__ ev,
               const float* __restrict__ W1, const float* __restrict__ b1) {
    __shared__ float sW1[4], sb1[4];
    int t = threadIdx.x;
    if (t < 4) { sW1[t] = W1[t]; sb1[t] = b1[t]; }
    __syncthreads();

    int m = blockIdx.x * blockDim.x + t;
    if (m >= M_NODES) return;

    float x = ev[m];
    float4 t4;
    t4.x = elu1(fmaf(x, sW1[0], sb1[0]));
    t4.y = elu1(fmaf(x, sW1[1], sb1[1]));
    t4.z = elu1(fmaf(x, sW1[2], sb1[2]));
    t4.w = elu1(fmaf(x, sW1[3], sb1[3]));
    reinterpret_cast<float4*>(g_t4)[m] = t4;

    float4 z4 = make_float4(0.f, 0.f, 0.f, 0.f);
    float4* uz = reinterpret_cast<float4*>(g_UZ + (size_t)m * 20);
#pragma unroll
    for (int k = 0; k < 5; k++) uz[k] = z4;
}

// ---------------------------------------------------------------------------
// dot2x14p: H1 = m1 . Prow(0..13) + Prow[14], H2 = m2 . Prow(0..13) + Prow[14]
// ONE row load (8 x LDS.128) serves BOTH dot chains.
// ---------------------------------------------------------------------------
__device__ __forceinline__ void dot2x14p(const ull* m1, const ull* m2v,
                                         const ull* Pr, ull& H1, ull& H2) {
    const ulonglong2* r2 = reinterpret_cast<const ulonglong2*>(Pr);
    ulonglong2 q0 = r2[0], q1 = r2[1], q2 = r2[2], q3 = r2[3];
    ulonglong2 q4 = r2[4], q5 = r2[5], q6 = r2[6], q7 = r2[7];

    ull a = mul2(m1[0], q0.x);
    fma2(a, m1[1], q0.y); fma2(a, m1[2], q1.x); fma2(a, m1[3], q1.y); fma2(a, m1[4], q2.x);
    ull b = mul2(m1[5], q2.y);
    fma2(b, m1[6], q3.x); fma2(b, m1[7], q3.y); fma2(b, m1[8], q4.x); fma2(b, m1[9], q4.y);
    ull c = mul2(m1[10], q5.x);
    fma2(c, m1[11], q5.y); fma2(c, m1[12], q6.x); fma2(c, m1[13], q6.y);
    H1 = add2(add2(a, b), add2(c, q7.x));

    ull d = mul2(m2v[0], q0.x);
    fma2(d, m2v[1], q0.y); fma2(d, m2v[2], q1.x); fma2(d, m2v[3], q1.y); fma2(d, m2v[4], q2.x);
    ull e = mul2(m2v[5], q2.y);
    fma2(e, m2v[6], q3.x); fma2(e, m2v[7], q3.y); fma2(e, m2v[8], q4.x); fma2(e, m2v[9], q4.y);
    ull f = mul2(m2v[10], q5.x);
    fma2(f, m2v[11], q5.y); fma2(f, m2v[12], q6.x); fma2(f, m2v[13], q6.y);
    H2 = add2(add2(d, e), add2(f, q7.x));
}

// scalar m_p for one edge, then dup-packed (head-pair lanes need identical m)
__device__ __forceinline__ void make_m_dup(const float4& ts, const float4& tq, ull* m) {
    m[0]  = dupf(ts.x * tq.x);
    m[1]  = dupf(fmaf(ts.x, tq.y, ts.y * tq.x));
    m[2]  = dupf(fmaf(ts.x, tq.z, ts.z * tq.x));
    m[3]  = dupf(fmaf(ts.x, tq.w, ts.w * tq.x));
    m[4]  = dupf(ts.x + tq.x);
    m[5]  = dupf(ts.y * tq.y);
    m[6]  = dupf(fmaf(ts.y, tq.z, ts.z * tq.y));
    m[7]  = dupf(fmaf(ts.y, tq.w, ts.w * tq.y));
    m[8]  = dupf(ts.y + tq.y);
    m[9]  = dupf(ts.z * tq.z);
    m[10] = dupf(fmaf(ts.z, tq.w, ts.w * tq.z));
    m[11] = dupf(ts.z + tq.z);
    m[12] = dupf(ts.w * tq.w);
    m[13] = dupf(ts.w + tq.w);
}

// ---------------------------------------------------------------------------
// Kernel B: TWO edges per thread; f32x2 lanes = (head h, head h+1).
// m dup-packed per edge; every P2-row load (8 LDS.128) feeds BOTH edges.
// ---------------------------------------------------------------------------
__global__ __launch_bounds__(128, 4)
void edge_kernel(const void* __restrict__ ei_raw,
                 const float* __restrict__ ef,
                 const float* __restrict__ W2, const float* __restrict__ b2) {
    __shared__ ull    sP2[544];        // [k][hp][p-pair], 4.25 KB
    __shared__ float4 sW2r[16];        // row k: (W2[0,k],W2[1,k],W2[2,k],W2[3,k])
    __shared__ float  sb2[16];

    int t = threadIdx.x;
    for (int i = t; i < 544; i += 128) sP2[i] = g_P2[i];
    if (t < 16) {
        sW2r[t] = make_float4(W2[t], W2[16 + t], W2[32 + t], W2[48 + t]);
        sb2[t] = b2[t];
    }
    __syncthreads();

    int ea = blockIdx.x * blockDim.x + t;
    if (ea >= NE_HALF) return;
    int eb = ea + NE_HALF;

    int srcA, dstA, srcB, dstB;
    if (g_idx_is_64) {
        const long long* ei = (const long long*)ei_raw;
        srcA = (int)__ldg(ei + ea);
        dstA = (int)__ldg(ei + NE_EDGES + ea);
        srcB = (int)__ldg(ei + eb);
        dstB = (int)__ldg(ei + NE_EDGES + eb);
    } else {
        const int* ei = (const int*)ei_raw;
        srcA = __ldg(ei + ea);
        dstA = __ldg(ei + NE_EDGES + ea);
        srcB = __ldg(ei + eb);
        dstB = __ldg(ei + NE_EDGES + eb);
    }

    const float4* t4p = reinterpret_cast<const float4*>(g_t4);
    float4 efA = __ldg(reinterpret_cast<const float4*>(ef) + ea);
    float4 efB = __ldg(reinterpret_cast<const float4*>(ef) + eb);

    // m tensors (dup-packed); ts/tq die after this block
    ull mA[14], mB[14];
    {
        float4 tsA = __ldg(t4p + srcA), tqA = __ldg(t4p + dstA);
        float4 tsB = __ldg(t4p + srcB), tqB = __ldg(t4p + dstB);
        make_m_dup(tsA, tqA, mA);
        make_m_dup(tsB, tqB, mB);
    }

    // sc[edge][hp], lanes = (h0,h1) / (h2,h3); init from bias row k=16
    ull scA[2], scB[2];
#pragma unroll
    for (int hp = 0; hp < 2; hp++)
        dot2x14p(mA, mB, sP2 + 16 * 32 + hp * 16, scA[hp], scB[hp]);

    // main k loop: e16 in-loop; each row load feeds both edges
#pragma unroll
    for (int k = 0; k < 16; k++) {
        float4 w = sW2r[k];
        float bb = sb2[k];
        float va = fmaf(efA.x, w.x, fmaf(efA.y, w.y, fmaf(efA.z, w.z, fmaf(efA.w, w.w, bb))));
        float vb = fmaf(efB.x, w.x, fmaf(efB.y, w.y, fmaf(efB.z, w.z, fmaf(efB.w, w.w, bb))));
        ull ekA = dupf(elu1(va));
        ull ekB = dupf(elu1(vb));
#pragma unroll
        for (int hp = 0; hp < 2; hp++) {
            ull HA, HB;
            dot2x14p(mA, mB, sP2 + k * 32 + hp * 16, HA, HB);
            fma2(scA[hp], ekA, HA);
            fma2(scB[hp], ekB, HB);
        }
    }

    // epilogue: re-gather ts (L1-hot), exp + scatter
    float4 tsA = __ldg(t4p + srcA);
    float4 tsB = __ldg(t4p + srcB);

    float* uzA = g_UZ + (size_t)dstA * 20;
    float* uzB = g_UZ + (size_t)dstB * 20;

    float sA0, sA1, sA2, sA3, sB0, sB1, sB2, sB3;
    upk2(sA0, sA1, scA[0]); upk2(sA2, sA3, scA[1]);
    upk2(sB0, sB1, scB[0]); upk2(sB2, sB3, scB[1]);

    float wA0 = __expf(fminf(fmaxf(sA0 * 0.25f, -5.0f), 5.0f));
    float wA1 = __expf(fminf(fmaxf(sA1 * 0.25f, -5.0f), 5.0f));
    float wA2 = __expf(fminf(fmaxf(sA2 * 0.25f, -5.0f), 5.0f));
    float wA3 = __expf(fminf(fmaxf(sA3 * 0.25f, -5.0f), 5.0f));
    float wB0 = __expf(fminf(fmaxf(sB0 * 0.25f, -5.0f), 5.0f));
    float wB1 = __expf(fminf(fmaxf(sB1 * 0.25f, -5.0f), 5.0f));
    float wB2 = __expf(fminf(fmaxf(sB2 * 0.25f, -5.0f), 5.0f));
    float wB3 = __expf(fminf(fmaxf(sB3 * 0.25f, -5.0f), 5.0f));

    red_add_v4(uzA +  0, make_float4(tsA.x * wA0, tsA.y * wA0, tsA.z * wA0, tsA.w * wA0));
    red_add_v4(uzA +  4, make_float4(tsA.x * wA1, tsA.y * wA1, tsA.z * wA1, tsA.w * wA1));
    red_add_v4(uzA +  8, make_float4(tsA.x * wA2, tsA.y * wA2, tsA.z * wA2, tsA.w * wA2));
    red_add_v4(uzA + 12, make_float4(tsA.x * wA3, tsA.y * wA3, tsA.z * wA3, tsA.w * wA3));
    red_add_v4(uzA + 16, make_float4(wA0, wA1, wA2, wA3));

    red_add_v4(uzB +  0, make_float4(tsB.x * wB0, tsB.y * wB0, tsB.z * wB0, tsB.w * wB0));
    red_add_v4(uzB +  4, make_float4(tsB.x * wB1, tsB.y * wB1, tsB.z * wB1, tsB.w * wB1));
    red_add_v4(uzB +  8, make_float4(tsB.x * wB2, tsB.y * wB2, tsB.z * wB2, tsB.w * wB2));
    red_add_v4(uzB + 12, make_float4(tsB.x * wB3, tsB.y * wB3, tsB.z * wB3, tsB.w * wB3));
    red_add_v4(uzB + 16, make_float4(wB0, wB1, wB2, wB3));
}

// ---------------------------------------------------------------------------
// Kernel C: wV_d = A[:,d].U_h + c_d*Z_h ; h_d = wV_d/(Z_h+1e-6);
//           out = elu(h @ Wout + bout) @ Wout1 + bout1
// ---------------------------------------------------------------------------
__global__ __launch_bounds__(256)
void out_kernel(float* __restrict__ out,
                const float* __restrict__ Wout,  const float* __restrict__ bout,
                const float* __restrict__ Wout1, const float* __restrict__ bout1) {
    __shared__ float sWo[1024], sbo[16], sW1[16], sb1, sA[256], sc_[64];
    int t = threadIdx.x;
    for (int i = t; i < 1024; i += blockDim.x) sWo[i] = Wout[i];
    if (t < 16) { sbo[t] = bout[t]; sW1[t] = Wout1[t]; }
    if (t == 0) sb1 = bout1[0];
    if (t < 256) sA[t] = g_A[t];
    if (t < 64)  sc_[t] = g_c[t];
    __syncthreads();

    int m = blockIdx.x * blockDim.x + t;
    if (m >= M_NODES) return;

    const float4* uz4 = reinterpret_cast<const float4*>(g_UZ + (size_t)m * 20);
    float4 U0 = uz4[0], U1 = uz4[1], U2 = uz4[2], U3 = uz4[3], Zv = uz4[4];
    float U[NHEADS][4] = {
        {U0.x, U0.y, U0.z, U0.w}, {U1.x, U1.y, U1.z, U1.w},
        {U2.x, U2.y, U2.z, U2.w}, {U3.x, U3.y, U3.z, U3.w}};
    float Z[NHEADS] = {Zv.x, Zv.y, Zv.z, Zv.w};

    float acc[16];
#pragma unroll
    for (int k = 0; k < 16; k++) acc[k] = sbo[k];

#pragma unroll
    for (int h = 0; h < NHEADS; h++) {
        float rz = 1.0f / (Z[h] + 1e-6f);
#pragma unroll
        for (int dd = 0; dd < 16; dd++) {
            int d = h * 16 + dd;
            float wv = sc_[d] * Z[h];
#pragma unroll
            for (int i = 0; i < 4; i++) wv = fmaf(sA[d * 4 + i], U[h][i], wv);
            float hv = wv * rz;
#pragma unroll
            for (int k = 0; k < 16; k++) acc[k] = fmaf(hv, sWo[d * 16 + k], acc[k]);
        }
    }

    float val = sb1;
#pragma unroll
    for (int k = 0; k < 16; k++) {
        float a = elu1(acc[k]);
        val = fmaf(a, sW1[k], val);
    }
    out[m] = val;
}

// ---------------------------------------------------------------------------
extern "C" void kernel_launch(void* const* d_in, const int* in_sizes, int n_in,
                              void* d_out, int out_size) {
    // order: node_attr, edge_index, edge_feature, edge_vector,
    //        W1, b1, W2, b2, W, b, Wout, bout, Wout1, bout1
    const void*  ei   = d_in[1];
    const float* ef   = (const float*)d_in[2];
    const float* ev   = (const float*)d_in[3];
    const float* W1   = (const float*)d_in[4];
    const float* b1   = (const float*)d_in[5];
    const float* W2   = (const float*)d_in[6];
    const float* b2   = (const float*)d_in[7];
    const float* W    = (const float*)d_in[8];
    const float* b    = (const float*)d_in[9];
    const float* Wout = (const float*)d_in[10];
    const float* bout = (const float*)d_in[11];
    const float* Wout1= (const float*)d_in[12];
    const float* bout1= (const float*)d_in[13];
    float* out = (float*)d_out;

    probe_idx_kernel<<<1, 1>>>((const int*)ei);
    setup_kernel<<<1, 256>>>(W2, b2, W, b);
    t4_kernel<<<(M_NODES + 255) / 256, 256>>>(ev, W1, b1);
    edge_kernel<<<(NE_HALF + 127) / 128, 128>>>(ei, ef, W2, b2);
    out_kernel<<<(M_NODES + 255) / 256, 256>>>(out, Wout, bout, Wout1, bout1);
}